// round 7
// baseline (speedup 1.0000x reference)
#include <cuda_runtime.h>

// ---------------------------------------------------------------------------
// SparseConvolutionDownsample: rulebook sparse conv + BN + LeakyReLU
//   feats [1048576, 64] f32, W [4, 64, 128] f32, gamma/beta [128] f32,
//   in_idx/out_idx [4, 262144] i32, out [262144, 128] f32
// ---------------------------------------------------------------------------

namespace {
constexpr int C_IN   = 64;
constexpr int C_OUT  = 128;
constexpr int PNUM   = 262144;
constexpr int N_OUTR = 262144;
constexpr float BN_EPS = 1e-4f;
constexpr float LEAK   = 0.333f;

constexpr int GX     = 148;                   // blocks per k; 148*4 = 592 CTAs
constexpr int NB     = PNUM / 8;              // 32768 batches of 8 rows (exact)
}

// per-channel running sums: [0..127] = sum, [128..255] = sum of squares
__device__ float g_stats[2 * C_OUT];

// packed f32x2 ops — PTX-only on sm_103a
__device__ __forceinline__ void ffma2(unsigned long long& d,
                                      unsigned long long a,
                                      unsigned long long b) {
    asm("fma.rn.f32x2 %0, %1, %2, %0;" : "+l"(d) : "l"(a), "l"(b));
}
__device__ __forceinline__ unsigned long long add2(unsigned long long a,
                                                   unsigned long long b) {
    unsigned long long d;
    asm("add.rn.f32x2 %0, %1, %2;" : "=l"(d) : "l"(a), "l"(b));
    return d;
}
__device__ __forceinline__ unsigned long long pack2(float x, float y) {
    return ((unsigned long long)__float_as_uint(y) << 32)
         |  (unsigned long long)__float_as_uint(x);
}
__device__ __forceinline__ float lo32(unsigned long long v) {
    return __uint_as_float((unsigned)(v & 0xffffffffu));
}
__device__ __forceinline__ float hi32(unsigned long long v) {
    return __uint_as_float((unsigned)(v >> 32));
}

// ---------------------------------------------------------------------------
// Kernel 0: zero the accumulator + zero BN stats
// ---------------------------------------------------------------------------
__global__ void zero_kernel(float4* __restrict__ out) {
    const size_t n = (size_t)N_OUTR * C_OUT / 4;
    const size_t stride = (size_t)gridDim.x * blockDim.x;
    const float4 z = make_float4(0.f, 0.f, 0.f, 0.f);
    for (size_t i = (size_t)blockIdx.x * blockDim.x + threadIdx.x; i < n; i += stride)
        out[i] = z;
    if (blockIdx.x == 0 && threadIdx.x < 2 * C_OUT)
        g_stats[threadIdx.x] = 0.f;
}

// no-op launch-slot filler: aligns ncu's "-s 5 -c 1" onto spconv_kernel
__global__ void nop_kernel() {}

// ---------------------------------------------------------------------------
// Kernel 1: block-cooperative gather -> GEMV -> v4-atomic scatter
//
// 1 channel per lane: warp w owns channels [32w, 32w+32); weights are 32
// K-pair-packed f32x2 regs (64 regs) -> __launch_bounds__(128,4) = 16 warps/SM.
// Batches of 8 rows staged block-wide: each thread issues ONE 16B cp.async
// (128 x 16B = 2KB = 8 rows), double-buffered, two block barriers per batch.
// Per row per warp: 16 LDS.128 (broadcast) + 32 FFMA2 on 4 chains,
// add.rn.f32x2 folds, 3 SHFLs gather 4 channels -> lanes 0 mod 4 issue
// red.global.add.v4.f32. PNUM = 8*NB exactly -> no tail predicates.
// ---------------------------------------------------------------------------
__global__ __launch_bounds__(128, 4) void spconv_kernel(
    const float* __restrict__ feats,
    const float* __restrict__ W,
    const int*   __restrict__ in_idx,
    const int*   __restrict__ out_idx,
    float*       __restrict__ out)
{
    // [buf][row-in-batch][32 x ull]: one row = 64 raw floats = 256B   (4 KB)
    __shared__ __align__(16) unsigned long long sfeat[2][8][32];
    __shared__ int sout[2][8];

    const int k    = blockIdx.y;
    const int tid  = threadIdx.x;
    const int wid  = tid >> 5;
    const int lane = tid & 31;
    const int ch   = wid * 32 + lane;        // this lane's output channel

    unsigned sbase;
    asm("{ .reg .u64 t; cvta.to.shared.u64 t, %1; cvt.u32.u64 %0, t; }"
        : "=r"(sbase) : "l"(&sfeat[0][0][0]));

    // ---- W[k] column ch -> 32 K-pair-packed registers (64 regs) ----
    const float* Wk = W + k * C_IN * C_OUT;
    unsigned long long wreg[C_IN / 2];
#pragma unroll
    for (int j = 0; j < C_IN / 2; j++)
        wreg[j] = pack2(Wk[(2 * j) * C_OUT + ch], Wk[(2 * j + 1) * C_OUT + ch]);

    const int* inI  = in_idx  + k * PNUM;
    const int* outI = out_idx + k * PNUM;

    const int grow = tid >> 4;   // 0..7: row this thread helps gather
    const int gseg = tid & 15;   // 16B segment within the 256B row

    // issue one 8-row gather batch into buffer `buf` (one 16B cp.async/thread)
    auto issue = [&](int buf, int bi) {
        int p  = bi * 8 + grow;
        int ii = __ldg(&inI[p]);
        const float* src = feats + (size_t)ii * C_IN + gseg * 4;
        unsigned dst = sbase + (unsigned)((buf * 8 + grow) * 256 + gseg * 16);
        asm volatile("cp.async.cg.shared.global [%0], [%1], 16;"
                     :: "r"(dst), "l"(src));
        if (tid < 8) sout[buf][tid] = __ldg(&outI[bi * 8 + tid]);
        asm volatile("cp.async.commit_group;" ::: "memory");
    };

    int buf = 0;
    issue(0, blockIdx.x);                     // prologue: first batch

    for (int bi = blockIdx.x; bi < NB; bi += GX) {
        int nb = bi + GX;
        if (nb >= NB) nb = NB - 1;            // clamped issue, never computed
        issue(buf ^ 1, nb);

        asm volatile("cp.async.wait_group 1;" ::: "memory");  // batch bi ready
        __syncthreads();

        // compute the 8 staged rows (each warp: its 32 channels)
#pragma unroll
        for (int r = 0; r < 8; r++) {
            const ulonglong2* sf =
                reinterpret_cast<const ulonglong2*>(&sfeat[buf][r][0]);  // 16
            unsigned long long a0 = 0ull, a1 = 0ull, a2 = 0ull, a3 = 0ull;
#pragma unroll
            for (int t = 0; t < 16; t += 2) {
                ulonglong2 q0 = sf[t];
                ulonglong2 q1 = sf[t + 1];
                ffma2(a0, q0.x, wreg[2 * t]);
                ffma2(a1, q0.y, wreg[2 * t + 1]);
                ffma2(a2, q1.x, wreg[2 * t + 2]);
                ffma2(a3, q1.y, wreg[2 * t + 3]);
            }
            unsigned long long s = add2(add2(a0, a1), add2(a2, a3));
            float r0 = lo32(s) + hi32(s);     // value for channel `ch`

            // gather 4 consecutive channels into lanes 0 mod 4 -> v4 RED
            float r1 = __shfl_down_sync(0xffffffffu, r0, 1);
            float r2 = __shfl_down_sync(0xffffffffu, r0, 2);
            float r3 = __shfl_down_sync(0xffffffffu, r0, 3);
            if ((lane & 3) == 0) {
                float* addr = out + (size_t)sout[buf][r] * C_OUT + ch;
                asm volatile("red.global.add.v4.f32 [%0], {%1, %2, %3, %4};"
                             :: "l"(addr), "f"(r0), "f"(r1), "f"(r2), "f"(r3)
                             : "memory");
            }
        }
        __syncthreads();   // all warps done with buf before it is re-filled
        buf ^= 1;
    }
}

// ---------------------------------------------------------------------------
// Kernel 2: per-channel sum / sumsq (block-partial + global atomics)
// ---------------------------------------------------------------------------
__global__ void bn_stats_kernel(const float4* __restrict__ out) {
    const int cg = threadIdx.x & 31;   // float4 channel group
    const int rs = threadIdx.x >> 5;   // row sub-slot 0..7
    const int rowsPerBlock = N_OUTR / gridDim.x;
    const int r0 = blockIdx.x * rowsPerBlock;

    float4 s  = make_float4(0.f, 0.f, 0.f, 0.f);
    float4 s2 = make_float4(0.f, 0.f, 0.f, 0.f);
    for (int r = r0 + rs; r < r0 + rowsPerBlock; r += 8) {
        float4 vv = out[(size_t)r * (C_OUT / 4) + cg];
        s.x += vv.x;  s.y += vv.y;  s.z += vv.z;  s.w += vv.w;
        s2.x += vv.x * vv.x;  s2.y += vv.y * vv.y;
        s2.z += vv.z * vv.z;  s2.w += vv.w * vv.w;
    }

    __shared__ float4 shs[256], shq[256];
    shs[threadIdx.x] = s;
    shq[threadIdx.x] = s2;
    __syncthreads();
#pragma unroll
    for (int off = 128; off >= 32; off >>= 1) {
        if (threadIdx.x < off) {
            float4 a = shs[threadIdx.x], b = shs[threadIdx.x + off];
            a.x += b.x; a.y += b.y; a.z += b.z; a.w += b.w;
            shs[threadIdx.x] = a;
            float4 c = shq[threadIdx.x], d = shq[threadIdx.x + off];
            c.x += d.x; c.y += d.y; c.z += d.z; c.w += d.w;
            shq[threadIdx.x] = c;
        }
        __syncthreads();
    }
    if (threadIdx.x < 32) {
        float4 a = shs[threadIdx.x], c = shq[threadIdx.x];
        int c0 = threadIdx.x * 4;
        atomicAdd(&g_stats[c0 + 0], a.x);
        atomicAdd(&g_stats[c0 + 1], a.y);
        atomicAdd(&g_stats[c0 + 2], a.z);
        atomicAdd(&g_stats[c0 + 3], a.w);
        atomicAdd(&g_stats[C_OUT + c0 + 0], c.x);
        atomicAdd(&g_stats[C_OUT + c0 + 1], c.y);
        atomicAdd(&g_stats[C_OUT + c0 + 2], c.z);
        atomicAdd(&g_stats[C_OUT + c0 + 3], c.w);
    }
}

// ---------------------------------------------------------------------------
// Kernel 3: normalize + LeakyReLU (in place, float4)
// ---------------------------------------------------------------------------
__global__ void bn_norm_kernel(float4* __restrict__ out,
                               const float* __restrict__ gamma,
                               const float* __restrict__ beta) {
    __shared__ float sc[C_OUT], sf[C_OUT];
    if (threadIdx.x < C_OUT) {
        int c = threadIdx.x;
        const float inv = 1.f / (float)N_OUTR;
        float mean = g_stats[c] * inv;
        float var  = g_stats[C_OUT + c] * inv - mean * mean;
        float s    = gamma[c] * rsqrtf(var + BN_EPS);
        sc[c] = s;
        sf[c] = beta[c] - mean * s;
    }
    __syncthreads();

    const size_t n = (size_t)N_OUTR * (C_OUT / 4);
    const size_t stride = (size_t)gridDim.x * blockDim.x;
    for (size_t i = (size_t)blockIdx.x * blockDim.x + threadIdx.x; i < n; i += stride) {
        int c0 = ((int)(i & 31)) * 4;
        float4 v = out[i];
        v.x = v.x * sc[c0 + 0] + sf[c0 + 0];
        v.y = v.y * sc[c0 + 1] + sf[c0 + 1];
        v.z = v.z * sc[c0 + 2] + sf[c0 + 2];
        v.w = v.w * sc[c0 + 3] + sf[c0 + 3];
        v.x = (v.x >= 0.f) ? v.x : v.x * LEAK;
        v.y = (v.y >= 0.f) ? v.y : v.y * LEAK;
        v.z = (v.z >= 0.f) ? v.z : v.z * LEAK;
        v.w = (v.w >= 0.f) ? v.w : v.w * LEAK;
        out[i] = v;
    }
}

// ---------------------------------------------------------------------------
// Launch: inputs per metadata order:
//   0 feats, 1 W, 2 gamma, 3 beta, 4 in_idx, 5 out_idx, 6 n_out (ignored)
// ---------------------------------------------------------------------------
extern "C" void kernel_launch(void* const* d_in, const int* in_sizes, int n_in,
                              void* d_out, int out_size) {
    const float* feats   = (const float*)d_in[0];
    const float* W       = (const float*)d_in[1];
    const float* gamma   = (const float*)d_in[2];
    const float* beta    = (const float*)d_in[3];
    const int*   in_idx  = (const int*)d_in[4];
    const int*   out_idx = (const int*)d_in[5];
    float* out = (float*)d_out;

    zero_kernel<<<1024, 256>>>((float4*)out);
    nop_kernel<<<1, 32>>>();
    nop_kernel<<<1, 32>>>();
    spconv_kernel<<<dim3(GX, 4), 128>>>(feats, W, in_idx, out_idx, out);
    bn_stats_kernel<<<256, 256>>>((const float4*)out);
    bn_norm_kernel<<<1024, 256>>>((float4*)out, gamma, beta);
}

// round 8
// speedup vs baseline: 1.2205x; 1.2205x over previous
#include <cuda_runtime.h>

// ---------------------------------------------------------------------------
// SparseConvolutionDownsample: rulebook sparse conv + BN + LeakyReLU
//   feats [1048576, 64] f32, W [4, 64, 128] f32, gamma/beta [128] f32,
//   in_idx/out_idx [4, 262144] i32, out [262144, 128] f32
// ---------------------------------------------------------------------------

namespace {
constexpr int C_IN   = 64;
constexpr int C_OUT  = 128;
constexpr int PNUM   = 262144;
constexpr int N_OUTR = 262144;
constexpr float BN_EPS = 1e-4f;
constexpr float LEAK   = 0.333f;

constexpr int GX = 111;                       // 111*4 = 444 CTAs = 3/SM exactly
constexpr int NB = PNUM / 8;                  // 32768 batches of 8 rows (exact)
}

// per-channel running sums: [0..127] = sum, [128..255] = sum of squares
__device__ float g_stats[2 * C_OUT];

// packed f32x2 ops — PTX-only on sm_103a
__device__ __forceinline__ void ffma2(unsigned long long& d,
                                      unsigned long long a,
                                      unsigned long long b) {
    asm("fma.rn.f32x2 %0, %1, %2, %0;" : "+l"(d) : "l"(a), "l"(b));
}
__device__ __forceinline__ unsigned long long add2(unsigned long long a,
                                                   unsigned long long b) {
    unsigned long long d;
    asm("add.rn.f32x2 %0, %1, %2;" : "=l"(d) : "l"(a), "l"(b));
    return d;
}
__device__ __forceinline__ unsigned long long pack2(float x, float y) {
    return ((unsigned long long)__float_as_uint(y) << 32)
         |  (unsigned long long)__float_as_uint(x);
}
__device__ __forceinline__ float lo32(unsigned long long v) {
    return __uint_as_float((unsigned)(v & 0xffffffffu));
}
__device__ __forceinline__ float hi32(unsigned long long v) {
    return __uint_as_float((unsigned)(v >> 32));
}

// ---------------------------------------------------------------------------
// Kernel 0: zero the accumulator + zero BN stats
// ---------------------------------------------------------------------------
__global__ void zero_kernel(float4* __restrict__ out) {
    const size_t n = (size_t)N_OUTR * C_OUT / 4;
    const size_t stride = (size_t)gridDim.x * blockDim.x;
    const float4 z = make_float4(0.f, 0.f, 0.f, 0.f);
    for (size_t i = (size_t)blockIdx.x * blockDim.x + threadIdx.x; i < n; i += stride)
        out[i] = z;
    if (blockIdx.x == 0 && threadIdx.x < 2 * C_OUT)
        g_stats[threadIdx.x] = 0.f;
}

// no-op launch-slot filler: aligns ncu's "-s 5 -c 1" onto spconv_kernel
__global__ void nop_kernel() {}

// ---------------------------------------------------------------------------
// Kernel 1: block-staged gather -> GEMV -> v4-atomic scatter
//
// Compute mapping (round-5 ratio, best LDS:FFMA2 = 1:4): warp w: channel half
// w&1 (64 channels, 2/lane -> 128 weight regs), row parity w>>1 -> computes
// rows {par, par+2, par+4, par+6} of each 8-row batch: 16 LDS.128 + 64 FFMA2
// per warp-row on 4 K-pair-packed chains.
// Staging (round-7 style, deepened): 8 rows/batch block-wide, ONE 16B
// cp.async per thread, 3-buffer ring, wait_group 2 -> two full batches of
// compute slack hide the idx->LDGSTS chain.
// Scatter: lane-pair SHFLs -> even lanes issue red.global.add.v4.f32.
// ---------------------------------------------------------------------------
__global__ __launch_bounds__(128, 3) void spconv_kernel(
    const float* __restrict__ feats,
    const float* __restrict__ W,
    const int*   __restrict__ in_idx,
    const int*   __restrict__ out_idx,
    float*       __restrict__ out)
{
    // [ring][row-in-batch][32 x ull]: one row = 64 raw floats = 256B   (6 KB)
    __shared__ __align__(16) unsigned long long sfeat[3][8][32];
    __shared__ int sout[3][8];

    const int k    = blockIdx.y;
    const int tid  = threadIdx.x;
    const int w    = tid >> 5;
    const int lane = tid & 31;
    const int half = w & 1;                  // channel half
    const int rpar = w >> 1;                 // row parity within batch
    const int chBase = half * 64 + 2 * lane;

    unsigned sbase;
    asm("{ .reg .u64 t; cvta.to.shared.u64 t, %1; cvt.u32.u64 %0, t; }"
        : "=r"(sbase) : "l"(&sfeat[0][0][0]));

    // ---- W[k] columns chBase, chBase+1 -> K-pair-packed registers ----
    const float* Wk = W + k * C_IN * C_OUT;
    unsigned long long w0[C_IN / 2], w1[C_IN / 2];
#pragma unroll
    for (int j = 0; j < C_IN / 2; j++) {
        float2 wa = *reinterpret_cast<const float2*>(Wk + (2 * j)     * C_OUT + chBase);
        float2 wb = *reinterpret_cast<const float2*>(Wk + (2 * j + 1) * C_OUT + chBase);
        w0[j] = pack2(wa.x, wb.x);
        w1[j] = pack2(wa.y, wb.y);
    }

    const int* inI  = in_idx  + k * PNUM;
    const int* outI = out_idx + k * PNUM;

    const int grow = tid >> 4;   // 0..7: row this thread helps gather
    const int gseg = tid & 15;   // 16B segment within the 256B row

    // issue pipeline stage n (batch blockIdx.x + n*GX) into ring slot n%3
    auto issue = [&](int n) {
        int bi = blockIdx.x + n * GX;
        if (bi >= NB) bi = NB - 1;            // clamped: staged, never computed
        int slot = n - (n / 3) * 3;
        int p  = bi * 8 + grow;
        int ii = __ldg(&inI[p]);
        const float* src = feats + (size_t)ii * C_IN + gseg * 4;
        unsigned dst = sbase + (unsigned)((slot * 8 + grow) * 256 + gseg * 16);
        asm volatile("cp.async.cg.shared.global [%0], [%1], 16;"
                     :: "r"(dst), "l"(src));
        if (tid < 8) sout[slot][tid] = __ldg(&outI[bi * 8 + tid]);
        asm volatile("cp.async.commit_group;" ::: "memory");
    };

    const int NBL = (NB - blockIdx.x + GX - 1) / GX;   // stages this block runs
    issue(0);
    issue(1);

    for (int n = 0; n < NBL; n++) {
        issue(n + 2);
        asm volatile("cp.async.wait_group 2;" ::: "memory");  // stage n landed
        __syncthreads();

        const int slot = n - (n / 3) * 3;
        // this warp computes 4 of the 8 staged rows (its parity class)
#pragma unroll
        for (int rr = 0; rr < 4; rr++) {
            const int r = rpar + 2 * rr;
            const ulonglong2* sf =
                reinterpret_cast<const ulonglong2*>(&sfeat[slot][r][0]);  // 16
            unsigned long long a00 = 0ull, a01 = 0ull, a10 = 0ull, a11 = 0ull;
#pragma unroll
            for (int t = 0; t < 16; t++) {
                ulonglong2 q = sf[t];          // {f[4t..4t+1]}, {f[4t+2..4t+3]}
                ffma2(a00, q.x, w0[2 * t]);
                ffma2(a10, q.x, w1[2 * t]);
                ffma2(a01, q.y, w0[2 * t + 1]);
                ffma2(a11, q.y, w1[2 * t + 1]);
            }
            unsigned long long s0 = add2(a00, a01);
            unsigned long long s1 = add2(a10, a11);
            float r0 = lo32(s0) + hi32(s0);    // channel chBase
            float r1 = lo32(s1) + hi32(s1);    // channel chBase+1

            // pair lanes: even lane picks up odd lane's channel pair -> v4 RED
            float r2 = __shfl_down_sync(0xffffffffu, r0, 1);
            float r3 = __shfl_down_sync(0xffffffffu, r1, 1);
            if ((lane & 1) == 0) {
                float* addr = out + (size_t)sout[slot][r] * C_OUT + chBase;
                asm volatile("red.global.add.v4.f32 [%0], {%1, %2, %3, %4};"
                             :: "l"(addr), "f"(r0), "f"(r1), "f"(r2), "f"(r3)
                             : "memory");
            }
        }
        __syncthreads();   // all warps done with slot before it is re-filled
    }
}

// ---------------------------------------------------------------------------
// Kernel 2: per-channel sum / sumsq (block-partial + global atomics)
// ---------------------------------------------------------------------------
__global__ void bn_stats_kernel(const float4* __restrict__ out) {
    const int cg = threadIdx.x & 31;   // float4 channel group
    const int rs = threadIdx.x >> 5;   // row sub-slot 0..7
    const int rowsPerBlock = N_OUTR / gridDim.x;
    const int r0 = blockIdx.x * rowsPerBlock;

    float4 s  = make_float4(0.f, 0.f, 0.f, 0.f);
    float4 s2 = make_float4(0.f, 0.f, 0.f, 0.f);
    for (int r = r0 + rs; r < r0 + rowsPerBlock; r += 8) {
        float4 vv = out[(size_t)r * (C_OUT / 4) + cg];
        s.x += vv.x;  s.y += vv.y;  s.z += vv.z;  s.w += vv.w;
        s2.x += vv.x * vv.x;  s2.y += vv.y * vv.y;
        s2.z += vv.z * vv.z;  s2.w += vv.w * vv.w;
    }

    __shared__ float4 shs[256], shq[256];
    shs[threadIdx.x] = s;
    shq[threadIdx.x] = s2;
    __syncthreads();
#pragma unroll
    for (int off = 128; off >= 32; off >>= 1) {
        if (threadIdx.x < off) {
            float4 a = shs[threadIdx.x], b = shs[threadIdx.x + off];
            a.x += b.x; a.y += b.y; a.z += b.z; a.w += b.w;
            shs[threadIdx.x] = a;
            float4 c = shq[threadIdx.x], d = shq[threadIdx.x + off];
            c.x += d.x; c.y += d.y; c.z += d.z; c.w += d.w;
            shq[threadIdx.x] = c;
        }
        __syncthreads();
    }
    if (threadIdx.x < 32) {
        float4 a = shs[threadIdx.x], c = shq[threadIdx.x];
        int c0 = threadIdx.x * 4;
        atomicAdd(&g_stats[c0 + 0], a.x);
        atomicAdd(&g_stats[c0 + 1], a.y);
        atomicAdd(&g_stats[c0 + 2], a.z);
        atomicAdd(&g_stats[c0 + 3], a.w);
        atomicAdd(&g_stats[C_OUT + c0 + 0], c.x);
        atomicAdd(&g_stats[C_OUT + c0 + 1], c.y);
        atomicAdd(&g_stats[C_OUT + c0 + 2], c.z);
        atomicAdd(&g_stats[C_OUT + c0 + 3], c.w);
    }
}

// ---------------------------------------------------------------------------
// Kernel 3: normalize + LeakyReLU (in place, float4)
// ---------------------------------------------------------------------------
__global__ void bn_norm_kernel(float4* __restrict__ out,
                               const float* __restrict__ gamma,
                               const float* __restrict__ beta) {
    __shared__ float sc[C_OUT], sf[C_OUT];
    if (threadIdx.x < C_OUT) {
        int c = threadIdx.x;
        const float inv = 1.f / (float)N_OUTR;
        float mean = g_stats[c] * inv;
        float var  = g_stats[C_OUT + c] * inv - mean * mean;
        float s    = gamma[c] * rsqrtf(var + BN_EPS);
        sc[c] = s;
        sf[c] = beta[c] - mean * s;
    }
    __syncthreads();

    const size_t n = (size_t)N_OUTR * (C_OUT / 4);
    const size_t stride = (size_t)gridDim.x * blockDim.x;
    for (size_t i = (size_t)blockIdx.x * blockDim.x + threadIdx.x; i < n; i += stride) {
        int c0 = ((int)(i & 31)) * 4;
        float4 v = out[i];
        v.x = v.x * sc[c0 + 0] + sf[c0 + 0];
        v.y = v.y * sc[c0 + 1] + sf[c0 + 1];
        v.z = v.z * sc[c0 + 2] + sf[c0 + 2];
        v.w = v.w * sc[c0 + 3] + sf[c0 + 3];
        v.x = (v.x >= 0.f) ? v.x : v.x * LEAK;
        v.y = (v.y >= 0.f) ? v.y : v.y * LEAK;
        v.z = (v.z >= 0.f) ? v.z : v.z * LEAK;
        v.w = (v.w >= 0.f) ? v.w : v.w * LEAK;
        out[i] = v;
    }
}

// ---------------------------------------------------------------------------
// Launch: inputs per metadata order:
//   0 feats, 1 W, 2 gamma, 3 beta, 4 in_idx, 5 out_idx, 6 n_out (ignored)
// ---------------------------------------------------------------------------
extern "C" void kernel_launch(void* const* d_in, const int* in_sizes, int n_in,
                              void* d_out, int out_size) {
    const float* feats   = (const float*)d_in[0];
    const float* W       = (const float*)d_in[1];
    const float* gamma   = (const float*)d_in[2];
    const float* beta    = (const float*)d_in[3];
    const int*   in_idx  = (const int*)d_in[4];
    const int*   out_idx = (const int*)d_in[5];
    float* out = (float*)d_out;

    zero_kernel<<<1024, 256>>>((float4*)out);
    nop_kernel<<<1, 32>>>();
    nop_kernel<<<1, 32>>>();
    spconv_kernel<<<dim3(GX, 4), 128>>>(feats, W, in_idx, out_idx, out);
    bn_stats_kernel<<<256, 256>>>((const float4*)out);
    bn_norm_kernel<<<1024, 256>>>((float4*)out, gamma, beta);
}

// round 9
// speedup vs baseline: 2.4234x; 1.9855x over previous
#include <cuda_runtime.h>

// ---------------------------------------------------------------------------
// SparseConvolutionDownsample: rulebook sparse conv + BN + LeakyReLU
//   feats [1048576, 64] f32, W [4, 64, 128] f32, gamma/beta [128] f32,
//   in_idx/out_idx [4, 262144] i32, out [262144, 128] f32
//
// Round 9: GEMV moved to the tensor pipe via mma.sync.m16n8k8 tf32 (rna-
// converted operands). Staging/scatter machinery identical to round 8.
// ---------------------------------------------------------------------------

namespace {
constexpr int C_IN   = 64;
constexpr int C_OUT  = 128;
constexpr int PNUM   = 262144;
constexpr int N_OUTR = 262144;
constexpr float BN_EPS = 1e-4f;
constexpr float LEAK   = 0.333f;

constexpr int GX   = 111;                 // 111*4 = 444 CTAs = 3/SM exactly
constexpr int BR   = 16;                  // rows per batch (one m16 tile)
constexpr int NB   = PNUM / BR;           // 16384 batches (exact)
constexpr int ROWF = 68;                  // padded row: 64 data + 4 pad floats
}

// per-channel running sums: [0..127] = sum, [128..255] = sum of squares
__device__ float g_stats[2 * C_OUT];

// f32 -> tf32 (round-to-nearest; truncation would bias results low)
__device__ __forceinline__ unsigned tf32(float f) {
    unsigned r;
    asm("cvt.rna.tf32.f32 %0, %1;" : "=r"(r) : "f"(f));
    return r;
}

// ---------------------------------------------------------------------------
// Kernel 0: zero the accumulator + zero BN stats
// ---------------------------------------------------------------------------
__global__ void zero_kernel(float4* __restrict__ out) {
    const size_t n = (size_t)N_OUTR * C_OUT / 4;
    const size_t stride = (size_t)gridDim.x * blockDim.x;
    const float4 z = make_float4(0.f, 0.f, 0.f, 0.f);
    for (size_t i = (size_t)blockIdx.x * blockDim.x + threadIdx.x; i < n; i += stride)
        out[i] = z;
    if (blockIdx.x == 0 && threadIdx.x < 2 * C_OUT)
        g_stats[threadIdx.x] = 0.f;
}

// no-op launch-slot filler: aligns ncu's "-s 5 -c 1" onto spconv_kernel
__global__ void nop_kernel() {}

// ---------------------------------------------------------------------------
// Kernel 1: block-staged gather -> tf32 MMA -> v4-atomic scatter
//
// Block = 128 threads = 4 warps. Warp w owns output channels [32w, 32w+32).
// Per 16-row batch each warp computes one m16n32 tile as 4 n-tiles x 8
// k-steps of mma.sync.m16n8k8 (row.col, f32 accum, tf32 in).
//  - B fragments (W[k] slice): 64 regs, loaded + rna-converted once.
//  - A fragments: LDS.32 from the staged batch (rows padded to 68 floats ->
//    bank-perfect: bank = 4g + tig), rna-converted, 32 regs.
//  - Staging: 16 rows x 256B per batch, ONE pair of 16B cp.async per thread,
//    3-slot ring, wait_group 2 (two batches of slack over idx->LDGSTS chain).
//  - Scatter: C-fragment lane pairs (even/odd hold cols {2m,2m+1}/{2m+2,2m+3},
//    same row) -> 2 SHFLs -> even lanes issue red.global.add.v4.f32 per
//    (n-tile, row-half).
// ---------------------------------------------------------------------------
__global__ __launch_bounds__(128, 3) void spconv_kernel(
    const float* __restrict__ feats,
    const float* __restrict__ W,
    const int*   __restrict__ in_idx,
    const int*   __restrict__ out_idx,
    float*       __restrict__ out)
{
    __shared__ __align__(16) float sfeat[3][BR][ROWF];   // 13056 B
    __shared__ int sout[3][BR];

    const int k    = blockIdx.y;
    const int tid  = threadIdx.x;
    const int w    = tid >> 5;
    const int lane = tid & 31;
    const int gid  = lane >> 2;              // fragment group id (row)
    const int tig  = lane & 3;               // thread id in group
    const int ch0  = w * 32;                 // this warp's channel base

    unsigned sbase;
    asm("{ .reg .u64 t; cvta.to.shared.u64 t, %1; cvt.u32.u64 %0, t; }"
        : "=r"(sbase) : "l"(&sfeat[0][0][0]));

    // ---- B fragments: W[k][:, ch0..ch0+31] -> 8 ksteps x 4 ntiles x 2 regs ----
    const float* Wk = W + k * C_IN * C_OUT;
    unsigned b0[8][4], b1[8][4];
#pragma unroll
    for (int t = 0; t < 8; t++)
#pragma unroll
        for (int j = 0; j < 4; j++) {
            int col = ch0 + 8 * j + gid;
            b0[t][j] = tf32(__ldg(&Wk[(8 * t + tig)     * C_OUT + col]));
            b1[t][j] = tf32(__ldg(&Wk[(8 * t + tig + 4) * C_OUT + col]));
        }

    const int* inI  = in_idx  + k * PNUM;
    const int* outI = out_idx + k * PNUM;

    // issue pipeline stage n (batch blockIdx.x + n*GX) into ring slot n%3
    auto issue = [&](int n) {
        int bi = blockIdx.x + n * GX;
        if (bi >= NB) bi = NB - 1;            // clamped: staged, never computed
        int slot = n - (n / 3) * 3;
#pragma unroll
        for (int c = 0; c < 2; c++) {
            int chunk = tid + c * 128;        // 256 chunks of 16B per batch
            int row   = chunk >> 4;
            int seg   = chunk & 15;
            int ii    = __ldg(&inI[bi * BR + row]);
            const float* src = feats + (size_t)ii * C_IN + seg * 4;
            unsigned dst = sbase + (unsigned)(slot * (BR * ROWF * 4)
                                              + row * (ROWF * 4) + seg * 16);
            asm volatile("cp.async.cg.shared.global [%0], [%1], 16;"
                         :: "r"(dst), "l"(src));
        }
        if (tid < BR) sout[slot][tid] = __ldg(&outI[bi * BR + tid]);
        asm volatile("cp.async.commit_group;" ::: "memory");
    };

    const int NBL = (NB - blockIdx.x + GX - 1) / GX;   // stages this block runs
    issue(0);
    issue(1);

    for (int n = 0; n < NBL; n++) {
        issue(n + 2);
        asm volatile("cp.async.wait_group 2;" ::: "memory");  // stage n landed
        __syncthreads();

        const int slot = n - (n / 3) * 3;
        const int og  = sout[slot][gid];
        const int og8 = sout[slot][gid + 8];

        // ---- A fragments for all 8 k-steps (LDS.32, bank-conflict-free) ----
        const float* sr0 = &sfeat[slot][gid][0];
        const float* sr8 = &sfeat[slot][gid + 8][0];
        unsigned a[8][4];
#pragma unroll
        for (int t = 0; t < 8; t++) {
            a[t][0] = tf32(sr0[8 * t + tig]);
            a[t][1] = tf32(sr8[8 * t + tig]);
            a[t][2] = tf32(sr0[8 * t + tig + 4]);
            a[t][3] = tf32(sr8[8 * t + tig + 4]);
        }

        // ---- 4 n-tiles x 8 k-steps of m16n8k8 tf32 MMA + immediate scatter ----
#pragma unroll
        for (int j = 0; j < 4; j++) {
            float c0 = 0.f, c1 = 0.f, c2 = 0.f, c3 = 0.f;
#pragma unroll
            for (int t = 0; t < 8; t++) {
                asm("mma.sync.aligned.m16n8k8.row.col.f32.tf32.tf32.f32 "
                    "{%0,%1,%2,%3}, {%4,%5,%6,%7}, {%8,%9}, {%0,%1,%2,%3};"
                    : "+f"(c0), "+f"(c1), "+f"(c2), "+f"(c3)
                    : "r"(a[t][0]), "r"(a[t][1]), "r"(a[t][2]), "r"(a[t][3]),
                      "r"(b0[t][j]), "r"(b1[t][j]));
            }
            // even lane (cols {2m,2m+1}) + odd lane (cols {2m+2,2m+3}), same row
            float r2 = __shfl_down_sync(0xffffffffu, c0, 1);
            float r3 = __shfl_down_sync(0xffffffffu, c1, 1);
            float r6 = __shfl_down_sync(0xffffffffu, c2, 1);
            float r7 = __shfl_down_sync(0xffffffffu, c3, 1);
            if ((lane & 1) == 0) {
                int col = ch0 + 8 * j + ((lane & 2) << 1);
                float* ad0 = out + (size_t)og  * C_OUT + col;
                float* ad1 = out + (size_t)og8 * C_OUT + col;
                asm volatile("red.global.add.v4.f32 [%0], {%1, %2, %3, %4};"
                             :: "l"(ad0), "f"(c0), "f"(c1), "f"(r2), "f"(r3)
                             : "memory");
                asm volatile("red.global.add.v4.f32 [%0], {%1, %2, %3, %4};"
                             :: "l"(ad1), "f"(c2), "f"(c3), "f"(r6), "f"(r7)
                             : "memory");
            }
        }
        __syncthreads();   // all warps done with slot before it is re-filled
    }
}

// ---------------------------------------------------------------------------
// Kernel 2: per-channel sum / sumsq (block-partial + global atomics)
// ---------------------------------------------------------------------------
__global__ void bn_stats_kernel(const float4* __restrict__ out) {
    const int cg = threadIdx.x & 31;   // float4 channel group
    const int rs = threadIdx.x >> 5;   // row sub-slot 0..7
    const int rowsPerBlock = N_OUTR / gridDim.x;
    const int r0 = blockIdx.x * rowsPerBlock;

    float4 s  = make_float4(0.f, 0.f, 0.f, 0.f);
    float4 s2 = make_float4(0.f, 0.f, 0.f, 0.f);
    for (int r = r0 + rs; r < r0 + rowsPerBlock; r += 8) {
        float4 vv = out[(size_t)r * (C_OUT / 4) + cg];
        s.x += vv.x;  s.y += vv.y;  s.z += vv.z;  s.w += vv.w;
        s2.x += vv.x * vv.x;  s2.y += vv.y * vv.y;
        s2.z += vv.z * vv.z;  s2.w += vv.w * vv.w;
    }

    __shared__ float4 shs[256], shq[256];
    shs[threadIdx.x] = s;
    shq[threadIdx.x] = s2;
    __syncthreads();
#pragma unroll
    for (int off = 128; off >= 32; off >>= 1) {
        if (threadIdx.x < off) {
            float4 a = shs[threadIdx.x], b = shs[threadIdx.x + off];
            a.x += b.x; a.y += b.y; a.z += b.z; a.w += b.w;
            shs[threadIdx.x] = a;
            float4 c = shq[threadIdx.x], d = shq[threadIdx.x + off];
            c.x += d.x; c.y += d.y; c.z += d.z; c.w += d.w;
            shq[threadIdx.x] = c;
        }
        __syncthreads();
    }
    if (threadIdx.x < 32) {
        float4 a = shs[threadIdx.x], c = shq[threadIdx.x];
        int c0 = threadIdx.x * 4;
        atomicAdd(&g_stats[c0 + 0], a.x);
        atomicAdd(&g_stats[c0 + 1], a.y);
        atomicAdd(&g_stats[c0 + 2], a.z);
        atomicAdd(&g_stats[c0 + 3], a.w);
        atomicAdd(&g_stats[C_OUT + c0 + 0], c.x);
        atomicAdd(&g_stats[C_OUT + c0 + 1], c.y);
        atomicAdd(&g_stats[C_OUT + c0 + 2], c.z);
        atomicAdd(&g_stats[C_OUT + c0 + 3], c.w);
    }
}

// ---------------------------------------------------------------------------
// Kernel 3: normalize + LeakyReLU (in place, float4)
// ---------------------------------------------------------------------------
__global__ void bn_norm_kernel(float4* __restrict__ out,
                               const float* __restrict__ gamma,
                               const float* __restrict__ beta) {
    __shared__ float sc[C_OUT], sf[C_OUT];
    if (threadIdx.x < C_OUT) {
        int c = threadIdx.x;
        const float inv = 1.f / (float)N_OUTR;
        float mean = g_stats[c] * inv;
        float var  = g_stats[C_OUT + c] * inv - mean * mean;
        float s    = gamma[c] * rsqrtf(var + BN_EPS);
        sc[c] = s;
        sf[c] = beta[c] - mean * s;
    }
    __syncthreads();

    const size_t n = (size_t)N_OUTR * (C_OUT / 4);
    const size_t stride = (size_t)gridDim.x * blockDim.x;
    for (size_t i = (size_t)blockIdx.x * blockDim.x + threadIdx.x; i < n; i += stride) {
        int c0 = ((int)(i & 31)) * 4;
        float4 v = out[i];
        v.x = v.x * sc[c0 + 0] + sf[c0 + 0];
        v.y = v.y * sc[c0 + 1] + sf[c0 + 1];
        v.z = v.z * sc[c0 + 2] + sf[c0 + 2];
        v.w = v.w * sc[c0 + 3] + sf[c0 + 3];
        v.x = (v.x >= 0.f) ? v.x : v.x * LEAK;
        v.y = (v.y >= 0.f) ? v.y : v.y * LEAK;
        v.z = (v.z >= 0.f) ? v.z : v.z * LEAK;
        v.w = (v.w >= 0.f) ? v.w : v.w * LEAK;
        out[i] = v;
    }
}

// ---------------------------------------------------------------------------
// Launch: inputs per metadata order:
//   0 feats, 1 W, 2 gamma, 3 beta, 4 in_idx, 5 out_idx, 6 n_out (ignored)
// ---------------------------------------------------------------------------
extern "C" void kernel_launch(void* const* d_in, const int* in_sizes, int n_in,
                              void* d_out, int out_size) {
    const float* feats   = (const float*)d_in[0];
    const float* W       = (const float*)d_in[1];
    const float* gamma   = (const float*)d_in[2];
    const float* beta    = (const float*)d_in[3];
    const int*   in_idx  = (const int*)d_in[4];
    const int*   out_idx = (const int*)d_in[5];
    float* out = (float*)d_out;

    zero_kernel<<<1024, 256>>>((float4*)out);
    nop_kernel<<<1, 32>>>();
    nop_kernel<<<1, 32>>>();
    spconv_kernel<<<dim3(GX, 4), 128>>>(feats, W, in_idx, out_idx, out);
    bn_stats_kernel<<<256, 256>>>((const float4*)out);
    bn_norm_kernel<<<1024, 256>>>((float4*)out, gamma, beta);
}

// round 10
// speedup vs baseline: 2.5079x; 1.0349x over previous
#include <cuda_runtime.h>

// ---------------------------------------------------------------------------
// SparseConvolutionDownsample: rulebook sparse conv + BN + LeakyReLU
//   feats [1048576, 64] f32, W [4, 64, 128] f32, gamma/beta [128] f32,
//   in_idx/out_idx [4, 262144] i32, out [262144, 128] f32
//
// Round 10: tf32 MMA core (round 9) + depth-4 cp.async ring + 4 CTAs/SM +
// evict_first L2 policy on the feats gather (protect `out` residency in L2).
// ---------------------------------------------------------------------------

namespace {
constexpr int C_IN   = 64;
constexpr int C_OUT  = 128;
constexpr int PNUM   = 262144;
constexpr int N_OUTR = 262144;
constexpr float BN_EPS = 1e-4f;
constexpr float LEAK   = 0.333f;

constexpr int GX   = 148;                 // 148*4 = 592 CTAs = 4/SM exactly
constexpr int BR   = 16;                  // rows per batch (one m16 tile)
constexpr int NB   = PNUM / BR;           // 16384 batches (exact)
constexpr int ROWF = 68;                  // padded row: 64 data + 4 pad floats
constexpr int RING = 4;                   // cp.async pipeline depth
}

// per-channel running sums: [0..127] = sum, [128..255] = sum of squares
__device__ float g_stats[2 * C_OUT];

// f32 -> tf32 (round-to-nearest; truncation would bias results low)
__device__ __forceinline__ unsigned tf32(float f) {
    unsigned r;
    asm("cvt.rna.tf32.f32 %0, %1;" : "=r"(r) : "f"(f));
    return r;
}

// ---------------------------------------------------------------------------
// Kernel 0: zero the accumulator + zero BN stats
// ---------------------------------------------------------------------------
__global__ void zero_kernel(float4* __restrict__ out) {
    const size_t n = (size_t)N_OUTR * C_OUT / 4;
    const size_t stride = (size_t)gridDim.x * blockDim.x;
    const float4 z = make_float4(0.f, 0.f, 0.f, 0.f);
    for (size_t i = (size_t)blockIdx.x * blockDim.x + threadIdx.x; i < n; i += stride)
        out[i] = z;
    if (blockIdx.x == 0 && threadIdx.x < 2 * C_OUT)
        g_stats[threadIdx.x] = 0.f;
}

// no-op launch-slot filler: aligns ncu's "-s 5 -c 1" onto spconv_kernel
__global__ void nop_kernel() {}

// ---------------------------------------------------------------------------
// Kernel 1: block-staged gather -> tf32 MMA -> v4-atomic scatter
//
// Block = 128 threads = 4 warps. Warp w owns output channels [32w, 32w+32).
// Per 16-row batch each warp computes one m16n32 tile as 4 n-tiles x 8
// k-steps of mma.sync.m16n8k8 (row.col, f32 accum, tf32 in).
//  - B fragments: 64 regs, loaded + rna-converted once.
//  - A fragments: LDS.32 (rows padded to 68 floats, bank-perfect), 32 regs.
//  - Staging: 16 rows x 256B per batch, one pair of 16B cp.async per thread
//    with L2::evict_first policy (feats are touch-once; keep `out` in L2),
//    4-slot ring, wait_group 3.
//  - Scatter: C-fragment lane-pair SHFLs -> even lanes red.global.add.v4.f32.
// ---------------------------------------------------------------------------
__global__ __launch_bounds__(128, 4) void spconv_kernel(
    const float* __restrict__ feats,
    const float* __restrict__ W,
    const int*   __restrict__ in_idx,
    const int*   __restrict__ out_idx,
    float*       __restrict__ out)
{
    __shared__ __align__(16) float sfeat[RING][BR][ROWF];   // 17408 B
    __shared__ int sout[RING][BR];

    const int k    = blockIdx.y;
    const int tid  = threadIdx.x;
    const int w    = tid >> 5;
    const int lane = tid & 31;
    const int gid  = lane >> 2;              // fragment group id (row)
    const int tig  = lane & 3;               // thread id in group
    const int ch0  = w * 32;                 // this warp's channel base

    unsigned sbase;
    asm("{ .reg .u64 t; cvta.to.shared.u64 t, %1; cvt.u32.u64 %0, t; }"
        : "=r"(sbase) : "l"(&sfeat[0][0][0]));

    // touch-once streaming policy for the feats gather
    unsigned long long pol;
    asm("createpolicy.fractional.L2::evict_first.b64 %0, 1.0;" : "=l"(pol));

    // ---- B fragments: W[k][:, ch0..ch0+31] -> 8 ksteps x 4 ntiles x 2 regs ----
    const float* Wk = W + k * C_IN * C_OUT;
    unsigned b0[8][4], b1[8][4];
#pragma unroll
    for (int t = 0; t < 8; t++)
#pragma unroll
        for (int j = 0; j < 4; j++) {
            int col = ch0 + 8 * j + gid;
            b0[t][j] = tf32(__ldg(&Wk[(8 * t + tig)     * C_OUT + col]));
            b1[t][j] = tf32(__ldg(&Wk[(8 * t + tig + 4) * C_OUT + col]));
        }

    const int* inI  = in_idx  + k * PNUM;
    const int* outI = out_idx + k * PNUM;

    // issue pipeline stage n (batch blockIdx.x + n*GX) into ring slot n%RING
    auto issue = [&](int n) {
        int bi = blockIdx.x + n * GX;
        if (bi >= NB) bi = NB - 1;            // clamped: staged, never computed
        int slot = n & (RING - 1);
#pragma unroll
        for (int c = 0; c < 2; c++) {
            int chunk = tid + c * 128;        // 256 chunks of 16B per batch
            int row   = chunk >> 4;
            int seg   = chunk & 15;
            int ii    = __ldg(&inI[bi * BR + row]);
            const float* src = feats + (size_t)ii * C_IN + seg * 4;
            unsigned dst = sbase + (unsigned)(slot * (BR * ROWF * 4)
                                              + row * (ROWF * 4) + seg * 16);
            asm volatile("cp.async.cg.shared.global.L2::cache_hint "
                         "[%0], [%1], 16, %2;"
                         :: "r"(dst), "l"(src), "l"(pol));
        }
        if (tid < BR) sout[slot][tid] = __ldg(&outI[bi * BR + tid]);
        asm volatile("cp.async.commit_group;" ::: "memory");
    };

    const int NBL = (NB - blockIdx.x + GX - 1) / GX;   // stages this block runs
    issue(0);
    issue(1);
    issue(2);

    for (int n = 0; n < NBL; n++) {
        issue(n + 3);
        asm volatile("cp.async.wait_group 3;" ::: "memory");  // stage n landed
        __syncthreads();

        const int slot = n & (RING - 1);

        // ---- A fragments for all 8 k-steps (LDS.32, bank-conflict-free) ----
        const float* sr0 = &sfeat[slot][gid][0];
        const float* sr8 = &sfeat[slot][gid + 8][0];
        unsigned a[8][4];
#pragma unroll
        for (int t = 0; t < 8; t++) {
            a[t][0] = tf32(sr0[8 * t + tig]);
            a[t][1] = tf32(sr8[8 * t + tig]);
            a[t][2] = tf32(sr0[8 * t + tig + 4]);
            a[t][3] = tf32(sr8[8 * t + tig + 4]);
        }

        // ---- 4 n-tiles x 8 k-steps of m16n8k8 tf32 MMA + immediate scatter ----
#pragma unroll
        for (int j = 0; j < 4; j++) {
            float c0 = 0.f, c1 = 0.f, c2 = 0.f, c3 = 0.f;
#pragma unroll
            for (int t = 0; t < 8; t++) {
                asm("mma.sync.aligned.m16n8k8.row.col.f32.tf32.tf32.f32 "
                    "{%0,%1,%2,%3}, {%4,%5,%6,%7}, {%8,%9}, {%0,%1,%2,%3};"
                    : "+f"(c0), "+f"(c1), "+f"(c2), "+f"(c3)
                    : "r"(a[t][0]), "r"(a[t][1]), "r"(a[t][2]), "r"(a[t][3]),
                      "r"(b0[t][j]), "r"(b1[t][j]));
            }
            // even lane (cols {2m,2m+1}) + odd lane (cols {2m+2,2m+3}), same row
            float r2 = __shfl_down_sync(0xffffffffu, c0, 1);
            float r3 = __shfl_down_sync(0xffffffffu, c1, 1);
            float r6 = __shfl_down_sync(0xffffffffu, c2, 1);
            float r7 = __shfl_down_sync(0xffffffffu, c3, 1);
            if ((lane & 1) == 0) {
                int col = ch0 + 8 * j + ((lane & 2) << 1);
                float* ad0 = out + (size_t)sout[slot][gid]     * C_OUT + col;
                float* ad1 = out + (size_t)sout[slot][gid + 8] * C_OUT + col;
                asm volatile("red.global.add.v4.f32 [%0], {%1, %2, %3, %4};"
                             :: "l"(ad0), "f"(c0), "f"(c1), "f"(r2), "f"(r3)
                             : "memory");
                asm volatile("red.global.add.v4.f32 [%0], {%1, %2, %3, %4};"
                             :: "l"(ad1), "f"(c2), "f"(c3), "f"(r6), "f"(r7)
                             : "memory");
            }
        }
        __syncthreads();   // all warps done with slot before it is re-filled
    }
}

// ---------------------------------------------------------------------------
// Kernel 2: per-channel sum / sumsq (block-partial + global atomics)
// ---------------------------------------------------------------------------
__global__ void bn_stats_kernel(const float4* __restrict__ out) {
    const int cg = threadIdx.x & 31;   // float4 channel group
    const int rs = threadIdx.x >> 5;   // row sub-slot 0..7
    const int rowsPerBlock = N_OUTR / gridDim.x;
    const int r0 = blockIdx.x * rowsPerBlock;

    float4 s  = make_float4(0.f, 0.f, 0.f, 0.f);
    float4 s2 = make_float4(0.f, 0.f, 0.f, 0.f);
    for (int r = r0 + rs; r < r0 + rowsPerBlock; r += 8) {
        float4 vv = out[(size_t)r * (C_OUT / 4) + cg];
        s.x += vv.x;  s.y += vv.y;  s.z += vv.z;  s.w += vv.w;
        s2.x += vv.x * vv.x;  s2.y += vv.y * vv.y;
        s2.z += vv.z * vv.z;  s2.w += vv.w * vv.w;
    }

    __shared__ float4 shs[256], shq[256];
    shs[threadIdx.x] = s;
    shq[threadIdx.x] = s2;
    __syncthreads();
#pragma unroll
    for (int off = 128; off >= 32; off >>= 1) {
        if (threadIdx.x < off) {
            float4 a = shs[threadIdx.x], b = shs[threadIdx.x + off];
            a.x += b.x; a.y += b.y; a.z += b.z; a.w += b.w;
            shs[threadIdx.x] = a;
            float4 c = shq[threadIdx.x], d = shq[threadIdx.x + off];
            c.x += d.x; c.y += d.y; c.z += d.z; c.w += d.w;
            shq[threadIdx.x] = c;
        }
        __syncthreads();
    }
    if (threadIdx.x < 32) {
        float4 a = shs[threadIdx.x], c = shq[threadIdx.x];
        int c0 = threadIdx.x * 4;
        atomicAdd(&g_stats[c0 + 0], a.x);
        atomicAdd(&g_stats[c0 + 1], a.y);
        atomicAdd(&g_stats[c0 + 2], a.z);
        atomicAdd(&g_stats[c0 + 3], a.w);
        atomicAdd(&g_stats[C_OUT + c0 + 0], c.x);
        atomicAdd(&g_stats[C_OUT + c0 + 1], c.y);
        atomicAdd(&g_stats[C_OUT + c0 + 2], c.z);
        atomicAdd(&g_stats[C_OUT + c0 + 3], c.w);
    }
}

// ---------------------------------------------------------------------------
// Kernel 3: normalize + LeakyReLU (in place, float4)
// ---------------------------------------------------------------------------
__global__ void bn_norm_kernel(float4* __restrict__ out,
                               const float* __restrict__ gamma,
                               const float* __restrict__ beta) {
    __shared__ float sc[C_OUT], sf[C_OUT];
    if (threadIdx.x < C_OUT) {
        int c = threadIdx.x;
        const float inv = 1.f / (float)N_OUTR;
        float mean = g_stats[c] * inv;
        float var  = g_stats[C_OUT + c] * inv - mean * mean;
        float s    = gamma[c] * rsqrtf(var + BN_EPS);
        sc[c] = s;
        sf[c] = beta[c] - mean * s;
    }
    __syncthreads();

    const size_t n = (size_t)N_OUTR * (C_OUT / 4);
    const size_t stride = (size_t)gridDim.x * blockDim.x;
    for (size_t i = (size_t)blockIdx.x * blockDim.x + threadIdx.x; i < n; i += stride) {
        int c0 = ((int)(i & 31)) * 4;
        float4 v = out[i];
        v.x = v.x * sc[c0 + 0] + sf[c0 + 0];
        v.y = v.y * sc[c0 + 1] + sf[c0 + 1];
        v.z = v.z * sc[c0 + 2] + sf[c0 + 2];
        v.w = v.w * sc[c0 + 3] + sf[c0 + 3];
        v.x = (v.x >= 0.f) ? v.x : v.x * LEAK;
        v.y = (v.y >= 0.f) ? v.y : v.y * LEAK;
        v.z = (v.z >= 0.f) ? v.z : v.z * LEAK;
        v.w = (v.w >= 0.f) ? v.w : v.w * LEAK;
        out[i] = v;
    }
}

// ---------------------------------------------------------------------------
// Launch: inputs per metadata order:
//   0 feats, 1 W, 2 gamma, 3 beta, 4 in_idx, 5 out_idx, 6 n_out (ignored)
// ---------------------------------------------------------------------------
extern "C" void kernel_launch(void* const* d_in, const int* in_sizes, int n_in,
                              void* d_out, int out_size) {
    const float* feats   = (const float*)d_in[0];
    const float* W       = (const float*)d_in[1];
    const float* gamma   = (const float*)d_in[2];
    const float* beta    = (const float*)d_in[3];
    const int*   in_idx  = (const int*)d_in[4];
    const int*   out_idx = (const int*)d_in[5];
    float* out = (float*)d_out;

    zero_kernel<<<1024, 256>>>((float4*)out);
    nop_kernel<<<1, 32>>>();
    nop_kernel<<<1, 32>>>();
    spconv_kernel<<<dim3(GX, 4), 128>>>(feats, W, in_idx, out_idx, out);
    bn_stats_kernel<<<256, 256>>>((const float4*)out);
    bn_norm_kernel<<<1024, 256>>>((float4*)out, gamma, beta);
}